// round 15
// baseline (speedup 1.0000x reference)
#include <cuda_runtime.h>
#include <cuda_bf16.h>
#include <stdint.h>

#define N_CAP 50000
#define E_CAP 1000000
#define H_CAP 128
#define C_CAP 64
#define KMAX  512
#define MPAD  (N_CAP + 128)

__device__ float g_dinv[N_CAP];
__device__ int   g_cnt[N_CAP];
__device__ int   g_rs[N_CAP];
__device__ int   g_cur[N_CAP];
__device__ int   g_bsum[64];
__device__ uint2 g_epay[E_CAP];
__device__ float g_h1[(size_t)N_CAP * H_CAP];
__device__ float g_o1[(size_t)N_CAP * H_CAP];
__device__ float g_h2[(size_t)N_CAP * C_CAP];
__device__ int   g_is64;
__device__ __nv_bfloat16 g_Bhi[H_CAP * KMAX];
__device__ __nv_bfloat16 g_Blo[H_CAP * KMAX];
__device__ __nv_bfloat16 g_Ahi[(size_t)MPAD * KMAX];
__device__ __nv_bfloat16 g_Alo[(size_t)MPAD * KMAX];

// ---------------------------------------------------------------------------
__device__ __forceinline__ void edge_rc(const void* ei, int is64, long long E,
                                        long long e, int& r, int& c) {
    if (is64) {
        const long long* p = (const long long*)ei;
        r = (int)p[e]; c = (int)p[E + e];
    } else {
        const int* p = (const int*)ei;
        r = p[e]; c = p[E + e];
    }
}

// init dinv/cnt/bsum, split+transpose W1, detect edge dtype — all independent.
__global__ void k_init_prep(const unsigned int* p, long long n32, int N,
                            const float* __restrict__ W1, int K) {
    int i = blockIdx.x * blockDim.x + threadIdx.x;
    if (i < N) { g_dinv[i] = 1.0f; g_cnt[i] = 0; }
    if (i < 64) g_bsum[i] = 0;                     // scan publish slots (per replay)
    if (i < K * 128) {
        int k = i >> 7, n = i & 127;
        float x = W1[(size_t)k * 128 + n];
        __nv_bfloat16 h = __float2bfloat16(x);
        __nv_bfloat16 l = __float2bfloat16(x - __bfloat162float(h));
        g_Bhi[(size_t)n * K + k] = h;
        g_Blo[(size_t)n * K + k] = l;
    }
    if (blockIdx.x == 0) {
        __shared__ unsigned int s;
        if (threadIdx.x == 0) s = 0u;
        __syncthreads();
        unsigned int v = 0u;
        long long lim = n32 < 16384 ? n32 : 16384;
        for (long long j = 1 + 2 * (long long)threadIdx.x; j < lim; j += 2 * (long long)blockDim.x)
            v |= p[j];
        atomicOr(&s, v);
        __syncthreads();
        if (threadIdx.x == 0) g_is64 = (s == 0u) ? 1 : 0;
    }
}

// ---------------------------------------------------------------------------
// Fused deg/count + A split-conversion, interleaved 1:8 block roles.
// ---------------------------------------------------------------------------
__global__ void k_deg_conv(const void* ei, const float* __restrict__ w, int E,
                           const float* __restrict__ feat, long long MK4,
                           int eb, long long convb) {
    int bid = blockIdx.x;
    int grp = bid / 9, rem = bid % 9;
    if (rem == 0) {
        if (grp < eb) {
            int e = grp * 256 + threadIdx.x;
            if (e < E) {
                int r, c;
                edge_rc(ei, g_is64, E, e, r, c);
                atomicAdd(&g_dinv[c], w[e]);
                atomicAdd(&g_cnt[c], 1);
            }
        }
    } else {
        long long cb = (long long)grp * 8 + (rem - 1);
        if (cb < convb) {
            long long i = cb * 256 + threadIdx.x;
            if (i < MK4) {
                float4 v = ((const float4*)feat)[i];
                __nv_bfloat16 hx = __float2bfloat16(v.x), hy = __float2bfloat16(v.y);
                __nv_bfloat16 hz = __float2bfloat16(v.z), hw = __float2bfloat16(v.w);
                __nv_bfloat16 lx = __float2bfloat16(v.x - __bfloat162float(hx));
                __nv_bfloat16 ly = __float2bfloat16(v.y - __bfloat162float(hy));
                __nv_bfloat16 lz = __float2bfloat16(v.z - __bfloat162float(hz));
                __nv_bfloat16 lw = __float2bfloat16(v.w - __bfloat162float(hw));
                __nv_bfloat162 h01(hx, hy), h23(hz, hw), l01(lx, ly), l23(lz, lw);
                ((uint2*)g_Ahi)[i] = make_uint2(*(uint32_t*)&h01, *(uint32_t*)&h23);
                ((uint2*)g_Alo)[i] = make_uint2(*(uint32_t*)&l01, *(uint32_t*)&l23);
            }
        }
    }
}

// ---------------------------------------------------------------------------
// Fused exclusive scan (+rsqrt): per-block scan, publish total+1, spin-read
// prior totals. 49 blocks all co-resident in wave 1 -> no deadlock.
// ---------------------------------------------------------------------------
__global__ __launch_bounds__(1024) void k_scan(int N) {
    __shared__ int wsum[32];
    __shared__ int boff;
    int tid = threadIdx.x, lane = tid & 31, w = tid >> 5;
    int idx = blockIdx.x * 1024 + tid;
    int v = (idx < N) ? g_cnt[idx] : 0;
    int x = v;
#pragma unroll
    for (int o = 1; o < 32; o <<= 1) {
        int t = __shfl_up_sync(0xffffffffu, x, o);
        if (lane >= o) x += t;
    }
    if (lane == 31) wsum[w] = x;
    __syncthreads();
    if (w == 0) {
        int s = wsum[lane];
#pragma unroll
        for (int o = 1; o < 32; o <<= 1) {
            int t = __shfl_up_sync(0xffffffffu, s, o);
            if (lane >= o) s += t;
        }
        wsum[lane] = s;
    }
    __syncthreads();
    int excl = x - v + (w ? wsum[w - 1] : 0);
    int total = wsum[31];
    if (tid == 0) {
        atomicExch(&g_bsum[blockIdx.x], total + 1);   // publish (nonzero flag)
        int off = 0;
        for (int b = 0; b < (int)blockIdx.x; b++) {
            int t;
            do { t = atomicAdd(&g_bsum[b], 0); } while (t == 0);
            off += t - 1;
        }
        boff = off;
    }
    __syncthreads();
    if (idx < N) {
        int val = excl + boff;
        g_rs[idx] = val;
        g_cur[idx] = val;
        g_dinv[idx] = rsqrtf(g_dinv[idx]);
    }
}

__global__ void k_fill(const void* ei, const float* __restrict__ w, int E) {
    int e = blockIdx.x * blockDim.x + threadIdx.x;
    if (e < E) {
        int r, c;
        edge_rc(ei, g_is64, E, e, r, c);
        float nr = g_dinv[r] * w[e] * g_dinv[c];
        int pos = atomicAdd(&g_cur[c], 1);
        g_epay[pos] = make_uint2((unsigned)r, __float_as_uint(nr));
    }
}

// ---------------------------------------------------------------------------
// GEMM1: 128x128 block, bf16-split mma.sync, cp.async double-buffered, k-tile 32.
// ---------------------------------------------------------------------------
#define AST3 40
#define STG3 (128 * AST3 * 2)
#define GSMEM (8 * STG3)

__device__ __forceinline__ void mma_bf16(float* c, const uint32_t* a, const uint32_t* b) {
    asm volatile(
        "mma.sync.aligned.m16n8k16.row.col.f32.bf16.bf16.f32 "
        "{%0,%1,%2,%3}, {%4,%5,%6,%7}, {%8,%9}, {%0,%1,%2,%3};"
        : "+f"(c[0]), "+f"(c[1]), "+f"(c[2]), "+f"(c[3])
        : "r"(a[0]), "r"(a[1]), "r"(a[2]), "r"(a[3]), "r"(b[0]), "r"(b[1]));
}
__device__ __forceinline__ void ldsm4(uint32_t* r, uint32_t addr) {
    asm volatile("ldmatrix.sync.aligned.m8n8.x4.shared.b16 {%0,%1,%2,%3}, [%4];"
                 : "=r"(r[0]), "=r"(r[1]), "=r"(r[2]), "=r"(r[3]) : "r"(addr));
}
__device__ __forceinline__ void cp16(uint32_t dst, const void* src) {
    asm volatile("cp.async.ca.shared.global [%0], [%1], 16;" :: "r"(dst), "l"(src));
}
__device__ __forceinline__ void cp_commit() {
    asm volatile("cp.async.commit_group;" ::: "memory");
}
template <int NN> __device__ __forceinline__ void cp_wait() {
    asm volatile("cp.async.wait_group %0;" :: "n"(NN) : "memory");
}

__global__ __launch_bounds__(256) void k_gemm1_mma(int M, int K) {
    extern __shared__ char dsm[];
    uint32_t sb = (uint32_t)__cvta_generic_to_shared(dsm);
    uint32_t uAhi = sb;
    uint32_t uAlo = sb + 2 * STG3;
    uint32_t uBhi = sb + 4 * STG3;
    uint32_t uBlo = sb + 6 * STG3;

    int tid = threadIdx.x, wid = tid >> 5, lane = tid & 31;
    int m0 = blockIdx.x * 128;
    int wm = (wid & 3) * 32;
    int wn = (wid >> 2) * 64;

    float acc[2][8][4];
#pragma unroll
    for (int i = 0; i < 2; i++)
#pragma unroll
        for (int j = 0; j < 8; j++)
#pragma unroll
            for (int q = 0; q < 4; q++) acc[i][j][q] = 0.0f;

    int a_row = (lane & 7) + ((lane >> 3) & 1) * 8;
    int a_kof = (lane >> 4) * 8;
    int b_row = (lane & 7) + ((lane >> 4) ? 8 : 0);
    int b_kof = ((lane >> 3) & 1) * 8;

    int row0 = tid >> 2, q0 = tid & 3;
    int row1 = (tid + 256) >> 2, q1 = (tid + 256) & 3;
    uint32_t d0 = (uint32_t)(row0 * AST3 + q0 * 8) * 2;
    uint32_t d1 = (uint32_t)(row1 * AST3 + q1 * 8) * 2;
    const __nv_bfloat16* aAhi0 = g_Ahi + (size_t)(m0 + row0) * K + q0 * 8;
    const __nv_bfloat16* aAhi1 = g_Ahi + (size_t)(m0 + row1) * K + q1 * 8;
    const __nv_bfloat16* aAlo0 = g_Alo + (size_t)(m0 + row0) * K + q0 * 8;
    const __nv_bfloat16* aAlo1 = g_Alo + (size_t)(m0 + row1) * K + q1 * 8;
    const __nv_bfloat16* aBhi0 = g_Bhi + (size_t)row0 * K + q0 * 8;
    const __nv_bfloat16* aBhi1 = g_Bhi + (size_t)row1 * K + q1 * 8;
    const __nv_bfloat16* aBlo0 = g_Blo + (size_t)row0 * K + q0 * 8;
    const __nv_bfloat16* aBlo1 = g_Blo + (size_t)row1 * K + q1 * 8;

    cp16(uAhi + d0, aAhi0); cp16(uAhi + d1, aAhi1);
    cp16(uAlo + d0, aAlo0); cp16(uAlo + d1, aAlo1);
    cp16(uBhi + d0, aBhi0); cp16(uBhi + d1, aBhi1);
    cp16(uBlo + d0, aBlo0); cp16(uBlo + d1, aBlo1);
    cp_commit();

    int ktiles = K >> 5;
    for (int kt = 0; kt < ktiles; kt++) {
        uint32_t so = (uint32_t)(kt & 1) * STG3;
        if (kt + 1 < ktiles) {
            uint32_t so2 = (uint32_t)((kt + 1) & 1) * STG3;
            int k1 = (kt + 1) << 5;
            cp16(uAhi + so2 + d0, aAhi0 + k1); cp16(uAhi + so2 + d1, aAhi1 + k1);
            cp16(uAlo + so2 + d0, aAlo0 + k1); cp16(uAlo + so2 + d1, aAlo1 + k1);
            cp16(uBhi + so2 + d0, aBhi0 + k1); cp16(uBhi + so2 + d1, aBhi1 + k1);
            cp16(uBlo + so2 + d0, aBlo0 + k1); cp16(uBlo + so2 + d1, aBlo1 + k1);
            cp_commit();
            cp_wait<1>();
        } else {
            cp_wait<0>();
        }
        __syncthreads();

#pragma unroll
        for (int ks = 0; ks < 32; ks += 16) {
            uint32_t ahif[2][4], alof[2][4];
#pragma unroll
            for (int mf = 0; mf < 2; mf++) {
                uint32_t off = so + (uint32_t)((wm + mf * 16 + a_row) * AST3 + ks + a_kof) * 2;
                ldsm4(ahif[mf], uAhi + off);
                ldsm4(alof[mf], uAlo + off);
            }
#pragma unroll
            for (int np = 0; np < 4; np++) {
                uint32_t off = so + (uint32_t)((wn + np * 16 + b_row) * AST3 + ks + b_kof) * 2;
                uint32_t bhf[4], blf[4];
                ldsm4(bhf, uBhi + off);
                ldsm4(blf, uBlo + off);
#pragma unroll
                for (int mf = 0; mf < 2; mf++) {
                    mma_bf16(acc[mf][np * 2], ahif[mf], bhf);
                    mma_bf16(acc[mf][np * 2], ahif[mf], blf);
                    mma_bf16(acc[mf][np * 2], alof[mf], bhf);
                    mma_bf16(acc[mf][np * 2 + 1], ahif[mf], bhf + 2);
                    mma_bf16(acc[mf][np * 2 + 1], ahif[mf], blf + 2);
                    mma_bf16(acc[mf][np * 2 + 1], alof[mf], bhf + 2);
                }
            }
        }
        __syncthreads();
    }

    int qr = lane >> 2, qc = (lane & 3) * 2;
#pragma unroll
    for (int mf = 0; mf < 2; mf++) {
        int r0 = m0 + wm + mf * 16 + qr;
#pragma unroll
        for (int nf = 0; nf < 8; nf++) {
            int cc = wn + nf * 8 + qc;
            if (r0 < M)
                *(float2*)(g_h1 + (size_t)r0 * 128 + cc) =
                    make_float2(acc[mf][nf][0], acc[mf][nf][1]);
            if (r0 + 8 < M)
                *(float2*)(g_h1 + (size_t)(r0 + 8) * 128 + cc) =
                    make_float2(acc[mf][nf][2], acc[mf][nf][3]);
        }
    }
}

// ---------------------------------------------------------------------------
// Layer-1: warp-per-node CSR gather (MLP-8), fused self+bias+relu -> o1
// ---------------------------------------------------------------------------
__global__ __launch_bounds__(256) void k_agg1_gather(const float* __restrict__ b1, int N) {
    int node = (blockIdx.x * blockDim.x + threadIdx.x) >> 5;
    int lane = threadIdx.x & 31;
    if (node >= N) return;
    int s = g_rs[node], e = s + g_cnt[node];
    float d = g_dinv[node];
    float4 acc = *(const float4*)(g_h1 + (size_t)node * 128 + lane * 4);
    float dd = d * d;
    acc.x *= dd; acc.y *= dd; acc.z *= dd; acc.w *= dd;
    int t = s;
    for (; t + 8 <= e; t += 8) {
        uint2 p[8];
        float4 v[8];
#pragma unroll
        for (int i = 0; i < 8; i++) p[i] = g_epay[t + i];
#pragma unroll
        for (int i = 0; i < 8; i++)
            v[i] = *(const float4*)(g_h1 + (size_t)p[i].x * 128 + lane * 4);
#pragma unroll
        for (int i = 0; i < 8; i++) {
            float nr = __uint_as_float(p[i].y);
            acc.x += nr * v[i].x; acc.y += nr * v[i].y;
            acc.z += nr * v[i].z; acc.w += nr * v[i].w;
        }
    }
    for (; t + 2 <= e; t += 2) {
        uint2 p0 = g_epay[t], p1 = g_epay[t + 1];
        float4 v0 = *(const float4*)(g_h1 + (size_t)p0.x * 128 + lane * 4);
        float4 v1 = *(const float4*)(g_h1 + (size_t)p1.x * 128 + lane * 4);
        float n0 = __uint_as_float(p0.y), n1 = __uint_as_float(p1.y);
        acc.x += n0 * v0.x + n1 * v1.x;
        acc.y += n0 * v0.y + n1 * v1.y;
        acc.z += n0 * v0.z + n1 * v1.z;
        acc.w += n0 * v0.w + n1 * v1.w;
    }
    if (t < e) {
        uint2 p = g_epay[t];
        float nr = __uint_as_float(p.y);
        float4 v = *(const float4*)(g_h1 + (size_t)p.x * 128 + lane * 4);
        acc.x += nr * v.x; acc.y += nr * v.y; acc.z += nr * v.z; acc.w += nr * v.w;
    }
    float4 bb = *(const float4*)(b1 + lane * 4);
    acc.x = fmaxf(acc.x + bb.x, 0.f);
    acc.y = fmaxf(acc.y + bb.y, 0.f);
    acc.z = fmaxf(acc.z + bb.z, 0.f);
    acc.w = fmaxf(acc.w + bb.w, 0.f);
    *(float4*)(g_o1 + (size_t)node * 128 + lane * 4) = acc;
}

// ---------------------------------------------------------------------------
// GEMM2: 256 threads, 2 nodes per warp (16 nodes/block) — amortize Ws load 4x.
// ---------------------------------------------------------------------------
__global__ __launch_bounds__(256) void k_gemm2(const float* __restrict__ W2, int N, int C) {
    __shared__ float Ws[128 * C_CAP];
    for (int i = threadIdx.x; i < 128 * C; i += blockDim.x) Ws[i] = W2[i];
    __syncthreads();
    int warp = threadIdx.x >> 5;
    int lane = threadIdx.x & 31;
    int nbase = blockIdx.x * 16 + warp * 2;
    int c1 = lane + 32;
    bool has1 = c1 < C;
    int cs = has1 ? c1 : lane;
#pragma unroll
    for (int sub = 0; sub < 2; sub++) {
        int n = nbase + sub;
        if (n >= N) break;
        float4 xq = *(const float4*)(g_o1 + (size_t)n * 128 + lane * 4);
        float a0 = 0.f, a1 = 0.f;
#pragma unroll
        for (int g = 0; g < 32; g++) {
            float x0 = __shfl_sync(0xffffffffu, xq.x, g);
            float x1 = __shfl_sync(0xffffffffu, xq.y, g);
            float x2 = __shfl_sync(0xffffffffu, xq.z, g);
            float x3 = __shfl_sync(0xffffffffu, xq.w, g);
            const float* w0 = Ws + (g * 4) * C;
            a0 += x0 * w0[lane] + x1 * w0[C + lane] + x2 * w0[2 * C + lane] + x3 * w0[3 * C + lane];
            a1 += x0 * w0[cs] + x1 * w0[C + cs] + x2 * w0[2 * C + cs] + x3 * w0[3 * C + cs];
        }
        g_h2[(size_t)n * C + lane] = a0;
        if (has1) g_h2[(size_t)n * C + c1] = a1;
    }
}

// ---------------------------------------------------------------------------
// Layer-2: warp-per-node gather (MLP-4) + self + bias + log_softmax -> out
// ---------------------------------------------------------------------------
__global__ __launch_bounds__(256) void k_agg2_gather(float* __restrict__ out,
                                                     const float* __restrict__ b2,
                                                     int N, int C) {
    int node = (blockIdx.x * blockDim.x + threadIdx.x) >> 5;
    int lane = threadIdx.x & 31;
    if (node >= N) return;
    int s = g_rs[node], e = s + g_cnt[node];
    float d = g_dinv[node];
    float dd = d * d;
    int c1 = lane + 32;
    bool has1 = c1 < C;
    const float* h0 = g_h2 + (size_t)node * C;
    float a0 = dd * h0[lane];
    float a1 = has1 ? dd * h0[c1] : 0.f;
    int t = s;
    for (; t + 4 <= e; t += 4) {
        uint2 p[4];
#pragma unroll
        for (int i = 0; i < 4; i++) p[i] = g_epay[t + i];
        float x0[4], x1[4];
#pragma unroll
        for (int i = 0; i < 4; i++) {
            const float* hp = g_h2 + (size_t)p[i].x * C;
            x0[i] = hp[lane];
            x1[i] = has1 ? hp[c1] : 0.f;
        }
#pragma unroll
        for (int i = 0; i < 4; i++) {
            float nr = __uint_as_float(p[i].y);
            a0 += nr * x0[i];
            if (has1) a1 += nr * x1[i];
        }
    }
    for (; t < e; t++) {
        uint2 p = g_epay[t];
        float nr = __uint_as_float(p.y);
        const float* hp = g_h2 + (size_t)p.x * C;
        a0 += nr * hp[lane];
        if (has1) a1 += nr * hp[c1];
    }
    a0 += b2[lane];
    if (has1) a1 += b2[c1];
    const float NEG_INF = __int_as_float(0xff800000);
    float v1 = has1 ? a1 : NEG_INF;
    float m = fmaxf(a0, v1);
#pragma unroll
    for (int o = 16; o > 0; o >>= 1) m = fmaxf(m, __shfl_xor_sync(0xffffffffu, m, o));
    float sum = expf(a0 - m) + (has1 ? expf(a1 - m) : 0.f);
#pragma unroll
    for (int o = 16; o > 0; o >>= 1) sum += __shfl_xor_sync(0xffffffffu, sum, o);
    float l = logf(sum);
    float* z = out + (size_t)node * C;
    z[lane] = a0 - m - l;
    if (has1) z[c1] = a1 - m - l;
}

// ---------------------------------------------------------------------------
extern "C" void kernel_launch(void* const* d_in, const int* in_sizes, int n_in,
                              void* d_out, int out_size) {
    const float* feat = (const float*)d_in[0];
    const void*  ei   = d_in[1];
    const float* ew   = (const float*)d_in[2];
    const float* W1   = (const float*)d_in[3];
    const float* b1   = (const float*)d_in[4];
    const float* W2   = (const float*)d_in[5];
    const float* b2   = (const float*)d_in[6];
    float* out = (float*)d_out;

    int H   = in_sizes[4];
    int FIN = in_sizes[3] / H;
    int N   = in_sizes[0] / FIN;
    int C   = in_sizes[6];
    int E   = in_sizes[2];
    (void)n_in; (void)out_size;

    int nsb = (N + 1023) / 1024;
    int initb = ((N > FIN * 128 ? N : FIN * 128) + 255) / 256;
    int eb = (E + 255) / 256;
    long long MK4 = (long long)N * FIN / 4;
    long long convb = (MK4 + 255) / 256;
    long long grp = eb > (convb + 7) / 8 ? eb : (convb + 7) / 8;
    int dcgrid = (int)(grp * 9);

    cudaFuncSetAttribute(k_gemm1_mma, cudaFuncAttributeMaxDynamicSharedMemorySize, GSMEM);

    k_init_prep<<<initb, 256>>>((const unsigned int*)ei, (long long)2 * E, N, W1, FIN);
    k_deg_conv<<<dcgrid, 256>>>(ei, ew, E, feat, MK4, eb, convb);
    k_scan<<<nsb, 1024>>>(N);
    k_gemm1_mma<<<(N + 127) / 128, 256, GSMEM>>>(N, FIN);
    k_fill<<<(E + 255) / 256, 256>>>(ei, ew, E);

    k_agg1_gather<<<(N + 7) / 8, 256>>>(b1, N);
    k_gemm2<<<(N + 15) / 16, 256>>>(W2, N, C);
    k_agg2_gather<<<(N + 7) / 8, 256>>>(out, b2, N, C);
}

// round 16
// speedup vs baseline: 1.0005x; 1.0005x over previous
#include <cuda_runtime.h>
#include <cuda_bf16.h>
#include <stdint.h>

#define N_CAP 50000
#define E_CAP 1000000
#define H_CAP 128
#define C_CAP 64
#define KMAX  512
#define MPAD  (N_CAP + 128)

__device__ float g_dinv[N_CAP];
__device__ int   g_cnt[N_CAP];
__device__ int   g_rs[N_CAP];
__device__ int   g_cur[N_CAP];
__device__ int   g_bsum[64];
__device__ uint2 g_epay[E_CAP];
__device__ float g_h1[(size_t)N_CAP * H_CAP];
__device__ float g_o1[(size_t)N_CAP * H_CAP];
__device__ float g_h2[(size_t)N_CAP * C_CAP];
__device__ int   g_is64;
__device__ __nv_bfloat16 g_Bhi[H_CAP * KMAX];
__device__ __nv_bfloat16 g_Blo[H_CAP * KMAX];
__device__ __nv_bfloat16 g_Ahi[(size_t)MPAD * KMAX];
__device__ __nv_bfloat16 g_Alo[(size_t)MPAD * KMAX];

// ---------------------------------------------------------------------------
__device__ __forceinline__ void edge_rc(const void* ei, int is64, long long E,
                                        long long e, int& r, int& c) {
    if (is64) {
        const long long* p = (const long long*)ei;
        r = (int)p[e]; c = (int)p[E + e];
    } else {
        const int* p = (const int*)ei;
        r = p[e]; c = p[E + e];
    }
}

// init dinv/cnt, split+transpose W1, detect edge dtype — all independent.
__global__ void k_init_prep(const unsigned int* p, long long n32, int N,
                            const float* __restrict__ W1, int K) {
    int i = blockIdx.x * blockDim.x + threadIdx.x;
    if (i < N) { g_dinv[i] = 1.0f; g_cnt[i] = 0; }
    if (i < K * 128) {
        int k = i >> 7, n = i & 127;
        float x = W1[(size_t)k * 128 + n];
        __nv_bfloat16 h = __float2bfloat16(x);
        __nv_bfloat16 l = __float2bfloat16(x - __bfloat162float(h));
        g_Bhi[(size_t)n * K + k] = h;
        g_Blo[(size_t)n * K + k] = l;
    }
    if (blockIdx.x == 0) {
        __shared__ unsigned int s;
        if (threadIdx.x == 0) s = 0u;
        __syncthreads();
        unsigned int v = 0u;
        long long lim = n32 < 16384 ? n32 : 16384;
        for (long long j = 1 + 2 * (long long)threadIdx.x; j < lim; j += 2 * (long long)blockDim.x)
            v |= p[j];
        atomicOr(&s, v);
        __syncthreads();
        if (threadIdx.x == 0) g_is64 = (s == 0u) ? 1 : 0;
    }
}

// ---------------------------------------------------------------------------
// Fused deg/count + A split-conversion, interleaved 1:8 block roles.
// ---------------------------------------------------------------------------
__global__ void k_deg_conv(const void* ei, const float* __restrict__ w, int E,
                           const float* __restrict__ feat, long long MK4,
                           int eb, long long convb) {
    int bid = blockIdx.x;
    int grp = bid / 9, rem = bid % 9;
    if (rem == 0) {
        if (grp < eb) {
            int e = grp * 256 + threadIdx.x;
            if (e < E) {
                int r, c;
                edge_rc(ei, g_is64, E, e, r, c);
                atomicAdd(&g_dinv[c], w[e]);
                atomicAdd(&g_cnt[c], 1);
            }
        }
    } else {
        long long cb = (long long)grp * 8 + (rem - 1);
        if (cb < convb) {
            long long i = cb * 256 + threadIdx.x;
            if (i < MK4) {
                float4 v = ((const float4*)feat)[i];
                __nv_bfloat16 hx = __float2bfloat16(v.x), hy = __float2bfloat16(v.y);
                __nv_bfloat16 hz = __float2bfloat16(v.z), hw = __float2bfloat16(v.w);
                __nv_bfloat16 lx = __float2bfloat16(v.x - __bfloat162float(hx));
                __nv_bfloat16 ly = __float2bfloat16(v.y - __bfloat162float(hy));
                __nv_bfloat16 lz = __float2bfloat16(v.z - __bfloat162float(hz));
                __nv_bfloat16 lw = __float2bfloat16(v.w - __bfloat162float(hw));
                __nv_bfloat162 h01(hx, hy), h23(hz, hw), l01(lx, ly), l23(lz, lw);
                ((uint2*)g_Ahi)[i] = make_uint2(*(uint32_t*)&h01, *(uint32_t*)&h23);
                ((uint2*)g_Alo)[i] = make_uint2(*(uint32_t*)&l01, *(uint32_t*)&l23);
            }
        }
    }
}

// ---------------------------------------------------------------------------
// Scan phase 1 (+fused rsqrt), phase 2  (two launches — measured faster than
// the fused spin-wait variant)
// ---------------------------------------------------------------------------
__global__ __launch_bounds__(1024) void k_scan1(int N) {
    __shared__ int wsum[32];
    int tid = threadIdx.x, lane = tid & 31, w = tid >> 5;
    int idx = blockIdx.x * 1024 + tid;
    int v = (idx < N) ? g_cnt[idx] : 0;
    int x = v;
#pragma unroll
    for (int o = 1; o < 32; o <<= 1) {
        int t = __shfl_up_sync(0xffffffffu, x, o);
        if (lane >= o) x += t;
    }
    if (lane == 31) wsum[w] = x;
    __syncthreads();
    if (w == 0) {
        int s = wsum[lane];
#pragma unroll
        for (int o = 1; o < 32; o <<= 1) {
            int t = __shfl_up_sync(0xffffffffu, s, o);
            if (lane >= o) s += t;
        }
        wsum[lane] = s;
    }
    __syncthreads();
    int excl = x - v + (w ? wsum[w - 1] : 0);
    if (idx < N) {
        g_rs[idx] = excl;
        g_dinv[idx] = rsqrtf(g_dinv[idx]);
    }
    if (tid == 1023) g_bsum[blockIdx.x] = excl + v;
}

__global__ __launch_bounds__(1024) void k_scan2(int N) {
    __shared__ int off;
    int tid = threadIdx.x;
    if (tid == 0) {
        int s = 0;
        for (int b = 0; b < (int)blockIdx.x; b++) s += g_bsum[b];
        off = s;
    }
    __syncthreads();
    int idx = blockIdx.x * 1024 + tid;
    if (idx < N) {
        int v = g_rs[idx] + off;
        g_rs[idx] = v;
        g_cur[idx] = v;
    }
}

__global__ void k_fill(const void* ei, const float* __restrict__ w, int E) {
    int e = blockIdx.x * blockDim.x + threadIdx.x;
    if (e < E) {
        int r, c;
        edge_rc(ei, g_is64, E, e, r, c);
        float nr = g_dinv[r] * w[e] * g_dinv[c];
        int pos = atomicAdd(&g_cur[c], 1);
        g_epay[pos] = make_uint2((unsigned)r, __float_as_uint(nr));
    }
}

// ---------------------------------------------------------------------------
// GEMM1: 128x128 block, bf16-split mma.sync, cp.async double-buffered, k-tile 32.
// ---------------------------------------------------------------------------
#define AST3 40
#define STG3 (128 * AST3 * 2)
#define GSMEM (8 * STG3)

__device__ __forceinline__ void mma_bf16(float* c, const uint32_t* a, const uint32_t* b) {
    asm volatile(
        "mma.sync.aligned.m16n8k16.row.col.f32.bf16.bf16.f32 "
        "{%0,%1,%2,%3}, {%4,%5,%6,%7}, {%8,%9}, {%0,%1,%2,%3};"
        : "+f"(c[0]), "+f"(c[1]), "+f"(c[2]), "+f"(c[3])
        : "r"(a[0]), "r"(a[1]), "r"(a[2]), "r"(a[3]), "r"(b[0]), "r"(b[1]));
}
__device__ __forceinline__ void ldsm4(uint32_t* r, uint32_t addr) {
    asm volatile("ldmatrix.sync.aligned.m8n8.x4.shared.b16 {%0,%1,%2,%3}, [%4];"
                 : "=r"(r[0]), "=r"(r[1]), "=r"(r[2]), "=r"(r[3]) : "r"(addr));
}
__device__ __forceinline__ void cp16(uint32_t dst, const void* src) {
    asm volatile("cp.async.ca.shared.global [%0], [%1], 16;" :: "r"(dst), "l"(src));
}
__device__ __forceinline__ void cp_commit() {
    asm volatile("cp.async.commit_group;" ::: "memory");
}
template <int NN> __device__ __forceinline__ void cp_wait() {
    asm volatile("cp.async.wait_group %0;" :: "n"(NN) : "memory");
}

__global__ __launch_bounds__(256) void k_gemm1_mma(int M, int K) {
    extern __shared__ char dsm[];
    uint32_t sb = (uint32_t)__cvta_generic_to_shared(dsm);
    uint32_t uAhi = sb;
    uint32_t uAlo = sb + 2 * STG3;
    uint32_t uBhi = sb + 4 * STG3;
    uint32_t uBlo = sb + 6 * STG3;

    int tid = threadIdx.x, wid = tid >> 5, lane = tid & 31;
    int m0 = blockIdx.x * 128;
    int wm = (wid & 3) * 32;
    int wn = (wid >> 2) * 64;

    float acc[2][8][4];
#pragma unroll
    for (int i = 0; i < 2; i++)
#pragma unroll
        for (int j = 0; j < 8; j++)
#pragma unroll
            for (int q = 0; q < 4; q++) acc[i][j][q] = 0.0f;

    int a_row = (lane & 7) + ((lane >> 3) & 1) * 8;
    int a_kof = (lane >> 4) * 8;
    int b_row = (lane & 7) + ((lane >> 4) ? 8 : 0);
    int b_kof = ((lane >> 3) & 1) * 8;

    int row0 = tid >> 2, q0 = tid & 3;
    int row1 = (tid + 256) >> 2, q1 = (tid + 256) & 3;
    uint32_t d0 = (uint32_t)(row0 * AST3 + q0 * 8) * 2;
    uint32_t d1 = (uint32_t)(row1 * AST3 + q1 * 8) * 2;
    const __nv_bfloat16* aAhi0 = g_Ahi + (size_t)(m0 + row0) * K + q0 * 8;
    const __nv_bfloat16* aAhi1 = g_Ahi + (size_t)(m0 + row1) * K + q1 * 8;
    const __nv_bfloat16* aAlo0 = g_Alo + (size_t)(m0 + row0) * K + q0 * 8;
    const __nv_bfloat16* aAlo1 = g_Alo + (size_t)(m0 + row1) * K + q1 * 8;
    const __nv_bfloat16* aBhi0 = g_Bhi + (size_t)row0 * K + q0 * 8;
    const __nv_bfloat16* aBhi1 = g_Bhi + (size_t)row1 * K + q1 * 8;
    const __nv_bfloat16* aBlo0 = g_Blo + (size_t)row0 * K + q0 * 8;
    const __nv_bfloat16* aBlo1 = g_Blo + (size_t)row1 * K + q1 * 8;

    cp16(uAhi + d0, aAhi0); cp16(uAhi + d1, aAhi1);
    cp16(uAlo + d0, aAlo0); cp16(uAlo + d1, aAlo1);
    cp16(uBhi + d0, aBhi0); cp16(uBhi + d1, aBhi1);
    cp16(uBlo + d0, aBlo0); cp16(uBlo + d1, aBlo1);
    cp_commit();

    int ktiles = K >> 5;
    for (int kt = 0; kt < ktiles; kt++) {
        uint32_t so = (uint32_t)(kt & 1) * STG3;
        if (kt + 1 < ktiles) {
            uint32_t so2 = (uint32_t)((kt + 1) & 1) * STG3;
            int k1 = (kt + 1) << 5;
            cp16(uAhi + so2 + d0, aAhi0 + k1); cp16(uAhi + so2 + d1, aAhi1 + k1);
            cp16(uAlo + so2 + d0, aAlo0 + k1); cp16(uAlo + so2 + d1, aAlo1 + k1);
            cp16(uBhi + so2 + d0, aBhi0 + k1); cp16(uBhi + so2 + d1, aBhi1 + k1);
            cp16(uBlo + so2 + d0, aBlo0 + k1); cp16(uBlo + so2 + d1, aBlo1 + k1);
            cp_commit();
            cp_wait<1>();
        } else {
            cp_wait<0>();
        }
        __syncthreads();

#pragma unroll
        for (int ks = 0; ks < 32; ks += 16) {
            uint32_t ahif[2][4], alof[2][4];
#pragma unroll
            for (int mf = 0; mf < 2; mf++) {
                uint32_t off = so + (uint32_t)((wm + mf * 16 + a_row) * AST3 + ks + a_kof) * 2;
                ldsm4(ahif[mf], uAhi + off);
                ldsm4(alof[mf], uAlo + off);
            }
#pragma unroll
            for (int np = 0; np < 4; np++) {
                uint32_t off = so + (uint32_t)((wn + np * 16 + b_row) * AST3 + ks + b_kof) * 2;
                uint32_t bhf[4], blf[4];
                ldsm4(bhf, uBhi + off);
                ldsm4(blf, uBlo + off);
#pragma unroll
                for (int mf = 0; mf < 2; mf++) {
                    mma_bf16(acc[mf][np * 2], ahif[mf], bhf);
                    mma_bf16(acc[mf][np * 2], ahif[mf], blf);
                    mma_bf16(acc[mf][np * 2], alof[mf], bhf);
                    mma_bf16(acc[mf][np * 2 + 1], ahif[mf], bhf + 2);
                    mma_bf16(acc[mf][np * 2 + 1], ahif[mf], blf + 2);
                    mma_bf16(acc[mf][np * 2 + 1], alof[mf], bhf + 2);
                }
            }
        }
        __syncthreads();
    }

    int qr = lane >> 2, qc = (lane & 3) * 2;
#pragma unroll
    for (int mf = 0; mf < 2; mf++) {
        int r0 = m0 + wm + mf * 16 + qr;
#pragma unroll
        for (int nf = 0; nf < 8; nf++) {
            int cc = wn + nf * 8 + qc;
            if (r0 < M)
                *(float2*)(g_h1 + (size_t)r0 * 128 + cc) =
                    make_float2(acc[mf][nf][0], acc[mf][nf][1]);
            if (r0 + 8 < M)
                *(float2*)(g_h1 + (size_t)(r0 + 8) * 128 + cc) =
                    make_float2(acc[mf][nf][2], acc[mf][nf][3]);
        }
    }
}

// ---------------------------------------------------------------------------
// Layer-1: warp-per-node CSR gather (MLP-8), fused self+bias+relu -> o1
// ---------------------------------------------------------------------------
__global__ __launch_bounds__(256) void k_agg1_gather(const float* __restrict__ b1, int N) {
    int node = (blockIdx.x * blockDim.x + threadIdx.x) >> 5;
    int lane = threadIdx.x & 31;
    if (node >= N) return;
    int s = g_rs[node], e = s + g_cnt[node];
    float d = g_dinv[node];
    float4 acc = *(const float4*)(g_h1 + (size_t)node * 128 + lane * 4);
    float dd = d * d;
    acc.x *= dd; acc.y *= dd; acc.z *= dd; acc.w *= dd;
    int t = s;
    for (; t + 8 <= e; t += 8) {
        uint2 p[8];
        float4 v[8];
#pragma unroll
        for (int i = 0; i < 8; i++) p[i] = g_epay[t + i];
#pragma unroll
        for (int i = 0; i < 8; i++)
            v[i] = *(const float4*)(g_h1 + (size_t)p[i].x * 128 + lane * 4);
#pragma unroll
        for (int i = 0; i < 8; i++) {
            float nr = __uint_as_float(p[i].y);
            acc.x += nr * v[i].x; acc.y += nr * v[i].y;
            acc.z += nr * v[i].z; acc.w += nr * v[i].w;
        }
    }
    for (; t + 2 <= e; t += 2) {
        uint2 p0 = g_epay[t], p1 = g_epay[t + 1];
        float4 v0 = *(const float4*)(g_h1 + (size_t)p0.x * 128 + lane * 4);
        float4 v1 = *(const float4*)(g_h1 + (size_t)p1.x * 128 + lane * 4);
        float n0 = __uint_as_float(p0.y), n1 = __uint_as_float(p1.y);
        acc.x += n0 * v0.x + n1 * v1.x;
        acc.y += n0 * v0.y + n1 * v1.y;
        acc.z += n0 * v0.z + n1 * v1.z;
        acc.w += n0 * v0.w + n1 * v1.w;
    }
    if (t < e) {
        uint2 p = g_epay[t];
        float nr = __uint_as_float(p.y);
        float4 v = *(const float4*)(g_h1 + (size_t)p.x * 128 + lane * 4);
        acc.x += nr * v.x; acc.y += nr * v.y; acc.z += nr * v.z; acc.w += nr * v.w;
    }
    float4 bb = *(const float4*)(b1 + lane * 4);
    acc.x = fmaxf(acc.x + bb.x, 0.f);
    acc.y = fmaxf(acc.y + bb.y, 0.f);
    acc.z = fmaxf(acc.z + bb.z, 0.f);
    acc.w = fmaxf(acc.w + bb.w, 0.f);
    *(float4*)(g_o1 + (size_t)node * 128 + lane * 4) = acc;
}

// ---------------------------------------------------------------------------
// GEMM2: persistent blocks — Ws loaded once per block, warps grid-stride
// over nodes (full warp parallelism, ~10x less Ws re-read than block-per-4).
// ---------------------------------------------------------------------------
__global__ __launch_bounds__(256) void k_gemm2(const float* __restrict__ W2, int N, int C,
                                               int nwtotal) {
    __shared__ float Ws[128 * C_CAP];
    for (int i = threadIdx.x; i < 128 * C; i += blockDim.x) Ws[i] = W2[i];
    __syncthreads();
    int warp = threadIdx.x >> 5;
    int lane = threadIdx.x & 31;
    int gw = blockIdx.x * 8 + warp;          // global warp id
    int c1 = lane + 32;
    bool has1 = c1 < C;
    int cs = has1 ? c1 : lane;
    for (int n = gw; n < N; n += nwtotal) {
        float4 xq = *(const float4*)(g_o1 + (size_t)n * 128 + lane * 4);
        float a0 = 0.f, a1 = 0.f;
#pragma unroll
        for (int g = 0; g < 32; g++) {
            float x0 = __shfl_sync(0xffffffffu, xq.x, g);
            float x1 = __shfl_sync(0xffffffffu, xq.y, g);
            float x2 = __shfl_sync(0xffffffffu, xq.z, g);
            float x3 = __shfl_sync(0xffffffffu, xq.w, g);
            const float* w0 = Ws + (g * 4) * C;
            a0 += x0 * w0[lane] + x1 * w0[C + lane] + x2 * w0[2 * C + lane] + x3 * w0[3 * C + lane];
            a1 += x0 * w0[cs] + x1 * w0[C + cs] + x2 * w0[2 * C + cs] + x3 * w0[3 * C + cs];
        }
        g_h2[(size_t)n * C + lane] = a0;
        if (has1) g_h2[(size_t)n * C + c1] = a1;
    }
}

// ---------------------------------------------------------------------------
// Layer-2: warp-per-node gather (MLP-2) + self + bias + log_softmax -> out
// ---------------------------------------------------------------------------
__global__ __launch_bounds__(256) void k_agg2_gather(float* __restrict__ out,
                                                     const float* __restrict__ b2,
                                                     int N, int C) {
    int node = (blockIdx.x * blockDim.x + threadIdx.x) >> 5;
    int lane = threadIdx.x & 31;
    if (node >= N) return;
    int s = g_rs[node], e = s + g_cnt[node];
    float d = g_dinv[node];
    float dd = d * d;
    int c1 = lane + 32;
    bool has1 = c1 < C;
    const float* h0 = g_h2 + (size_t)node * C;
    float a0 = dd * h0[lane];
    float a1 = has1 ? dd * h0[c1] : 0.f;
    int t = s;
    for (; t + 2 <= e; t += 2) {
        uint2 p0 = g_epay[t], p1 = g_epay[t + 1];
        const float* hp0 = g_h2 + (size_t)p0.x * C;
        const float* hp1 = g_h2 + (size_t)p1.x * C;
        float n0 = __uint_as_float(p0.y), n1 = __uint_as_float(p1.y);
        a0 += n0 * hp0[lane] + n1 * hp1[lane];
        if (has1) a1 += n0 * hp0[c1] + n1 * hp1[c1];
    }
    for (; t < e; t++) {
        uint2 p = g_epay[t];
        float nr = __uint_as_float(p.y);
        const float* hp = g_h2 + (size_t)p.x * C;
        a0 += nr * hp[lane];
        if (has1) a1 += nr * hp[c1];
    }
    a0 += b2[lane];
    if (has1) a1 += b2[c1];
    const float NEG_INF = __int_as_float(0xff800000);
    float v1 = has1 ? a1 : NEG_INF;
    float m = fmaxf(a0, v1);
#pragma unroll
    for (int o = 16; o > 0; o >>= 1) m = fmaxf(m, __shfl_xor_sync(0xffffffffu, m, o));
    float sum = expf(a0 - m) + (has1 ? expf(a1 - m) : 0.f);
#pragma unroll
    for (int o = 16; o > 0; o >>= 1) sum += __shfl_xor_sync(0xffffffffu, sum, o);
    float l = logf(sum);
    float* z = out + (size_t)node * C;
    z[lane] = a0 - m - l;
    if (has1) z[c1] = a1 - m - l;
}

// ---------------------------------------------------------------------------
extern "C" void kernel_launch(void* const* d_in, const int* in_sizes, int n_in,
                              void* d_out, int out_size) {
    const float* feat = (const float*)d_in[0];
    const void*  ei   = d_in[1];
    const float* ew   = (const float*)d_in[2];
    const float* W1   = (const float*)d_in[3];
    const float* b1   = (const float*)d_in[4];
    const float* W2   = (const float*)d_in[5];
    const float* b2   = (const float*)d_in[6];
    float* out = (float*)d_out;

    int H   = in_sizes[4];
    int FIN = in_sizes[3] / H;
    int N   = in_sizes[0] / FIN;
    int C   = in_sizes[6];
    int E   = in_sizes[2];
    (void)n_in; (void)out_size;

    int nsb = (N + 1023) / 1024;
    int initb = ((N > FIN * 128 ? N : FIN * 128) + 255) / 256;
    int eb = (E + 255) / 256;
    long long MK4 = (long long)N * FIN / 4;
    long long convb = (MK4 + 255) / 256;
    long long grp = eb > (convb + 7) / 8 ? eb : (convb + 7) / 8;
    int dcgrid = (int)(grp * 9);

    cudaFuncSetAttribute(k_gemm1_mma, cudaFuncAttributeMaxDynamicSharedMemorySize, GSMEM);

    k_init_prep<<<initb, 256>>>((const unsigned int*)ei, (long long)2 * E, N, W1, FIN);
    k_deg_conv<<<dcgrid, 256>>>(ei, ew, E, feat, MK4, eb, convb);
    k_scan1<<<nsb, 1024>>>(N);
    k_gemm1_mma<<<(N + 127) / 128, 256, GSMEM>>>(N, FIN);
    k_scan2<<<nsb, 1024>>>(N);
    k_fill<<<(E + 255) / 256, 256>>>(ei, ew, E);

    k_agg1_gather<<<(N + 7) / 8, 256>>>(b1, N);
    int g2b = 1184;                        // ~8 blocks/SM, persistent
    k_gemm2<<<g2b, 256>>>(W2, N, C, g2b * 8);
    k_agg2_gather<<<(N + 7) / 8, 256>>>(out, b2, N, C);
}

// round 17
// speedup vs baseline: 1.0906x; 1.0900x over previous
#include <cuda_runtime.h>
#include <cuda_bf16.h>
#include <stdint.h>

#define N_CAP 50000
#define E_CAP 1000000
#define H_CAP 128
#define C_CAP 64
#define KMAX  512
#define MPAD  (N_CAP + 128)

__device__ float g_dinv[N_CAP];
__device__ int   g_cnt[N_CAP];
__device__ int   g_rs[N_CAP];
__device__ int   g_cur[N_CAP];
__device__ int   g_bsum[64];
__device__ uint2 g_epay[E_CAP];
__device__ float g_h1[(size_t)N_CAP * H_CAP];
__device__ float g_o1[(size_t)N_CAP * H_CAP];
__device__ float g_h2[(size_t)N_CAP * C_CAP];
__device__ int   g_is64;
__device__ __nv_bfloat16 g_Bhi[H_CAP * KMAX];
__device__ __nv_bfloat16 g_Blo[H_CAP * KMAX];
__device__ __nv_bfloat16 g_Ahi[(size_t)MPAD * KMAX];
__device__ __nv_bfloat16 g_Alo[(size_t)MPAD * KMAX];

// ---------------------------------------------------------------------------
__device__ __forceinline__ void edge_rc(const void* ei, int is64, long long E,
                                        long long e, int& r, int& c) {
    if (is64) {
        const long long* p = (const long long*)ei;
        r = (int)p[e]; c = (int)p[E + e];
    } else {
        const int* p = (const int*)ei;
        r = p[e]; c = p[E + e];
    }
}

// init dinv/cnt, split+transpose W1, detect edge dtype — all independent.
__global__ void k_init_prep(const unsigned int* p, long long n32, int N,
                            const float* __restrict__ W1, int K) {
    int i = blockIdx.x * blockDim.x + threadIdx.x;
    if (i < N) { g_dinv[i] = 1.0f; g_cnt[i] = 0; }
    if (i < K * 128) {
        int k = i >> 7, n = i & 127;
        float x = W1[(size_t)k * 128 + n];
        __nv_bfloat16 h = __float2bfloat16(x);
        __nv_bfloat16 l = __float2bfloat16(x - __bfloat162float(h));
        g_Bhi[(size_t)n * K + k] = h;
        g_Blo[(size_t)n * K + k] = l;
    }
    if (blockIdx.x == 0) {
        __shared__ unsigned int s;
        if (threadIdx.x == 0) s = 0u;
        __syncthreads();
        unsigned int v = 0u;
        long long lim = n32 < 16384 ? n32 : 16384;
        for (long long j = 1 + 2 * (long long)threadIdx.x; j < lim; j += 2 * (long long)blockDim.x)
            v |= p[j];
        atomicOr(&s, v);
        __syncthreads();
        if (threadIdx.x == 0) g_is64 = (s == 0u) ? 1 : 0;
    }
}

// ---------------------------------------------------------------------------
// Fused deg/count + A split-conversion, interleaved 1:8 block roles.
// ---------------------------------------------------------------------------
__global__ void k_deg_conv(const void* ei, const float* __restrict__ w, int E,
                           const float* __restrict__ feat, long long MK4,
                           int eb, long long convb) {
    int bid = blockIdx.x;
    int grp = bid / 9, rem = bid % 9;
    if (rem == 0) {
        if (grp < eb) {
            int e = grp * 256 + threadIdx.x;
            if (e < E) {
                int r, c;
                edge_rc(ei, g_is64, E, e, r, c);
                atomicAdd(&g_dinv[c], w[e]);
                atomicAdd(&g_cnt[c], 1);
            }
        }
    } else {
        long long cb = (long long)grp * 8 + (rem - 1);
        if (cb < convb) {
            long long i = cb * 256 + threadIdx.x;
            if (i < MK4) {
                float4 v = ((const float4*)feat)[i];
                __nv_bfloat16 hx = __float2bfloat16(v.x), hy = __float2bfloat16(v.y);
                __nv_bfloat16 hz = __float2bfloat16(v.z), hw = __float2bfloat16(v.w);
                __nv_bfloat16 lx = __float2bfloat16(v.x - __bfloat162float(hx));
                __nv_bfloat16 ly = __float2bfloat16(v.y - __bfloat162float(hy));
                __nv_bfloat16 lz = __float2bfloat16(v.z - __bfloat162float(hz));
                __nv_bfloat16 lw = __float2bfloat16(v.w - __bfloat162float(hw));
                __nv_bfloat162 h01(hx, hy), h23(hz, hw), l01(lx, ly), l23(lz, lw);
                ((uint2*)g_Ahi)[i] = make_uint2(*(uint32_t*)&h01, *(uint32_t*)&h23);
                ((uint2*)g_Alo)[i] = make_uint2(*(uint32_t*)&l01, *(uint32_t*)&l23);
            }
        }
    }
}

// ---------------------------------------------------------------------------
// Scan phase 1 (+fused rsqrt), phase 2
// ---------------------------------------------------------------------------
__global__ __launch_bounds__(1024) void k_scan1(int N) {
    __shared__ int wsum[32];
    int tid = threadIdx.x, lane = tid & 31, w = tid >> 5;
    int idx = blockIdx.x * 1024 + tid;
    int v = (idx < N) ? g_cnt[idx] : 0;
    int x = v;
#pragma unroll
    for (int o = 1; o < 32; o <<= 1) {
        int t = __shfl_up_sync(0xffffffffu, x, o);
        if (lane >= o) x += t;
    }
    if (lane == 31) wsum[w] = x;
    __syncthreads();
    if (w == 0) {
        int s = wsum[lane];
#pragma unroll
        for (int o = 1; o < 32; o <<= 1) {
            int t = __shfl_up_sync(0xffffffffu, s, o);
            if (lane >= o) s += t;
        }
        wsum[lane] = s;
    }
    __syncthreads();
    int excl = x - v + (w ? wsum[w - 1] : 0);
    if (idx < N) {
        g_rs[idx] = excl;
        g_dinv[idx] = rsqrtf(g_dinv[idx]);
    }
    if (tid == 1023) g_bsum[blockIdx.x] = excl + v;
}

__global__ __launch_bounds__(1024) void k_scan2(int N) {
    __shared__ int off;
    int tid = threadIdx.x;
    if (tid == 0) {
        int s = 0;
        for (int b = 0; b < (int)blockIdx.x; b++) s += g_bsum[b];
        off = s;
    }
    __syncthreads();
    int idx = blockIdx.x * 1024 + tid;
    if (idx < N) {
        int v = g_rs[idx] + off;
        g_rs[idx] = v;
        g_cur[idx] = v;
    }
}

__global__ void k_fill(const void* ei, const float* __restrict__ w, int E) {
    int e = blockIdx.x * blockDim.x + threadIdx.x;
    if (e < E) {
        int r, c;
        edge_rc(ei, g_is64, E, e, r, c);
        float nr = g_dinv[r] * w[e] * g_dinv[c];
        int pos = atomicAdd(&g_cur[c], 1);
        g_epay[pos] = make_uint2((unsigned)r, __float_as_uint(nr));
    }
}

// ---------------------------------------------------------------------------
// GEMM1: 128x128 block, bf16-split mma.sync, cp.async double-buffered, k-tile 32.
// ---------------------------------------------------------------------------
#define AST3 40
#define STG3 (128 * AST3 * 2)
#define GSMEM (8 * STG3)

__device__ __forceinline__ void mma_bf16(float* c, const uint32_t* a, const uint32_t* b) {
    asm volatile(
        "mma.sync.aligned.m16n8k16.row.col.f32.bf16.bf16.f32 "
        "{%0,%1,%2,%3}, {%4,%5,%6,%7}, {%8,%9}, {%0,%1,%2,%3};"
        : "+f"(c[0]), "+f"(c[1]), "+f"(c[2]), "+f"(c[3])
        : "r"(a[0]), "r"(a[1]), "r"(a[2]), "r"(a[3]), "r"(b[0]), "r"(b[1]));
}
__device__ __forceinline__ void ldsm4(uint32_t* r, uint32_t addr) {
    asm volatile("ldmatrix.sync.aligned.m8n8.x4.shared.b16 {%0,%1,%2,%3}, [%4];"
                 : "=r"(r[0]), "=r"(r[1]), "=r"(r[2]), "=r"(r[3]) : "r"(addr));
}
__device__ __forceinline__ void cp16(uint32_t dst, const void* src) {
    asm volatile("cp.async.ca.shared.global [%0], [%1], 16;" :: "r"(dst), "l"(src));
}
__device__ __forceinline__ void cp_commit() {
    asm volatile("cp.async.commit_group;" ::: "memory");
}
template <int NN> __device__ __forceinline__ void cp_wait() {
    asm volatile("cp.async.wait_group %0;" :: "n"(NN) : "memory");
}

__global__ __launch_bounds__(256) void k_gemm1_mma(int M, int K) {
    extern __shared__ char dsm[];
    uint32_t sb = (uint32_t)__cvta_generic_to_shared(dsm);
    uint32_t uAhi = sb;
    uint32_t uAlo = sb + 2 * STG3;
    uint32_t uBhi = sb + 4 * STG3;
    uint32_t uBlo = sb + 6 * STG3;

    int tid = threadIdx.x, wid = tid >> 5, lane = tid & 31;
    int m0 = blockIdx.x * 128;
    int wm = (wid & 3) * 32;
    int wn = (wid >> 2) * 64;

    float acc[2][8][4];
#pragma unroll
    for (int i = 0; i < 2; i++)
#pragma unroll
        for (int j = 0; j < 8; j++)
#pragma unroll
            for (int q = 0; q < 4; q++) acc[i][j][q] = 0.0f;

    int a_row = (lane & 7) + ((lane >> 3) & 1) * 8;
    int a_kof = (lane >> 4) * 8;
    int b_row = (lane & 7) + ((lane >> 4) ? 8 : 0);
    int b_kof = ((lane >> 3) & 1) * 8;

    int row0 = tid >> 2, q0 = tid & 3;
    int row1 = (tid + 256) >> 2, q1 = (tid + 256) & 3;
    uint32_t d0 = (uint32_t)(row0 * AST3 + q0 * 8) * 2;
    uint32_t d1 = (uint32_t)(row1 * AST3 + q1 * 8) * 2;
    const __nv_bfloat16* aAhi0 = g_Ahi + (size_t)(m0 + row0) * K + q0 * 8;
    const __nv_bfloat16* aAhi1 = g_Ahi + (size_t)(m0 + row1) * K + q1 * 8;
    const __nv_bfloat16* aAlo0 = g_Alo + (size_t)(m0 + row0) * K + q0 * 8;
    const __nv_bfloat16* aAlo1 = g_Alo + (size_t)(m0 + row1) * K + q1 * 8;
    const __nv_bfloat16* aBhi0 = g_Bhi + (size_t)row0 * K + q0 * 8;
    const __nv_bfloat16* aBhi1 = g_Bhi + (size_t)row1 * K + q1 * 8;
    const __nv_bfloat16* aBlo0 = g_Blo + (size_t)row0 * K + q0 * 8;
    const __nv_bfloat16* aBlo1 = g_Blo + (size_t)row1 * K + q1 * 8;

    cp16(uAhi + d0, aAhi0); cp16(uAhi + d1, aAhi1);
    cp16(uAlo + d0, aAlo0); cp16(uAlo + d1, aAlo1);
    cp16(uBhi + d0, aBhi0); cp16(uBhi + d1, aBhi1);
    cp16(uBlo + d0, aBlo0); cp16(uBlo + d1, aBlo1);
    cp_commit();

    int ktiles = K >> 5;
    for (int kt = 0; kt < ktiles; kt++) {
        uint32_t so = (uint32_t)(kt & 1) * STG3;
        if (kt + 1 < ktiles) {
            uint32_t so2 = (uint32_t)((kt + 1) & 1) * STG3;
            int k1 = (kt + 1) << 5;
            cp16(uAhi + so2 + d0, aAhi0 + k1); cp16(uAhi + so2 + d1, aAhi1 + k1);
            cp16(uAlo + so2 + d0, aAlo0 + k1); cp16(uAlo + so2 + d1, aAlo1 + k1);
            cp16(uBhi + so2 + d0, aBhi0 + k1); cp16(uBhi + so2 + d1, aBhi1 + k1);
            cp16(uBlo + so2 + d0, aBlo0 + k1); cp16(uBlo + so2 + d1, aBlo1 + k1);
            cp_commit();
            cp_wait<1>();
        } else {
            cp_wait<0>();
        }
        __syncthreads();

#pragma unroll
        for (int ks = 0; ks < 32; ks += 16) {
            uint32_t ahif[2][4], alof[2][4];
#pragma unroll
            for (int mf = 0; mf < 2; mf++) {
                uint32_t off = so + (uint32_t)((wm + mf * 16 + a_row) * AST3 + ks + a_kof) * 2;
                ldsm4(ahif[mf], uAhi + off);
                ldsm4(alof[mf], uAlo + off);
            }
#pragma unroll
            for (int np = 0; np < 4; np++) {
                uint32_t off = so + (uint32_t)((wn + np * 16 + b_row) * AST3 + ks + b_kof) * 2;
                uint32_t bhf[4], blf[4];
                ldsm4(bhf, uBhi + off);
                ldsm4(blf, uBlo + off);
#pragma unroll
                for (int mf = 0; mf < 2; mf++) {
                    mma_bf16(acc[mf][np * 2], ahif[mf], bhf);
                    mma_bf16(acc[mf][np * 2], ahif[mf], blf);
                    mma_bf16(acc[mf][np * 2], alof[mf], bhf);
                    mma_bf16(acc[mf][np * 2 + 1], ahif[mf], bhf + 2);
                    mma_bf16(acc[mf][np * 2 + 1], ahif[mf], blf + 2);
                    mma_bf16(acc[mf][np * 2 + 1], alof[mf], bhf + 2);
                }
            }
        }
        __syncthreads();
    }

    int qr = lane >> 2, qc = (lane & 3) * 2;
#pragma unroll
    for (int mf = 0; mf < 2; mf++) {
        int r0 = m0 + wm + mf * 16 + qr;
#pragma unroll
        for (int nf = 0; nf < 8; nf++) {
            int cc = wn + nf * 8 + qc;
            if (r0 < M)
                *(float2*)(g_h1 + (size_t)r0 * 128 + cc) =
                    make_float2(acc[mf][nf][0], acc[mf][nf][1]);
            if (r0 + 8 < M)
                *(float2*)(g_h1 + (size_t)(r0 + 8) * 128 + cc) =
                    make_float2(acc[mf][nf][2], acc[mf][nf][3]);
        }
    }
}

// ---------------------------------------------------------------------------
// Layer-1: warp-per-node CSR gather (MLP-8), fused self+bias+relu -> o1
// ---------------------------------------------------------------------------
__global__ __launch_bounds__(256) void k_agg1_gather(const float* __restrict__ b1, int N) {
    int node = (blockIdx.x * blockDim.x + threadIdx.x) >> 5;
    int lane = threadIdx.x & 31;
    if (node >= N) return;
    int s = g_rs[node], e = s + g_cnt[node];
    float d = g_dinv[node];
    float4 acc = *(const float4*)(g_h1 + (size_t)node * 128 + lane * 4);
    float dd = d * d;
    acc.x *= dd; acc.y *= dd; acc.z *= dd; acc.w *= dd;
    int t = s;
    for (; t + 8 <= e; t += 8) {
        uint2 p[8];
        float4 v[8];
#pragma unroll
        for (int i = 0; i < 8; i++) p[i] = g_epay[t + i];
#pragma unroll
        for (int i = 0; i < 8; i++)
            v[i] = *(const float4*)(g_h1 + (size_t)p[i].x * 128 + lane * 4);
#pragma unroll
        for (int i = 0; i < 8; i++) {
            float nr = __uint_as_float(p[i].y);
            acc.x += nr * v[i].x; acc.y += nr * v[i].y;
            acc.z += nr * v[i].z; acc.w += nr * v[i].w;
        }
    }
    for (; t + 2 <= e; t += 2) {
        uint2 p0 = g_epay[t], p1 = g_epay[t + 1];
        float4 v0 = *(const float4*)(g_h1 + (size_t)p0.x * 128 + lane * 4);
        float4 v1 = *(const float4*)(g_h1 + (size_t)p1.x * 128 + lane * 4);
        float n0 = __uint_as_float(p0.y), n1 = __uint_as_float(p1.y);
        acc.x += n0 * v0.x + n1 * v1.x;
        acc.y += n0 * v0.y + n1 * v1.y;
        acc.z += n0 * v0.z + n1 * v1.z;
        acc.w += n0 * v0.w + n1 * v1.w;
    }
    if (t < e) {
        uint2 p = g_epay[t];
        float nr = __uint_as_float(p.y);
        float4 v = *(const float4*)(g_h1 + (size_t)p.x * 128 + lane * 4);
        acc.x += nr * v.x; acc.y += nr * v.y; acc.z += nr * v.z; acc.w += nr * v.w;
    }
    float4 bb = *(const float4*)(b1 + lane * 4);
    acc.x = fmaxf(acc.x + bb.x, 0.f);
    acc.y = fmaxf(acc.y + bb.y, 0.f);
    acc.z = fmaxf(acc.z + bb.z, 0.f);
    acc.w = fmaxf(acc.w + bb.w, 0.f);
    *(float4*)(g_o1 + (size_t)node * 128 + lane * 4) = acc;
}

// ---------------------------------------------------------------------------
// GEMM2: warp-per-node (R14 schedule), 8 warps/block — halves Ws fill passes.
// ---------------------------------------------------------------------------
__global__ __launch_bounds__(256) void k_gemm2(const float* __restrict__ W2, int N, int C) {
    __shared__ float Ws[128 * C_CAP];
    for (int i = threadIdx.x; i < 128 * C; i += blockDim.x) Ws[i] = W2[i];
    __syncthreads();
    int warp = threadIdx.x >> 5;
    int lane = threadIdx.x & 31;
    int n = blockIdx.x * 8 + warp;
    if (n >= N) return;
    float4 xq = *(const float4*)(g_o1 + (size_t)n * 128 + lane * 4);
    float a0 = 0.f, a1 = 0.f;
    int c1 = lane + 32;
    bool has1 = c1 < C;
    int cs = has1 ? c1 : lane;
#pragma unroll
    for (int g = 0; g < 32; g++) {
        float x0 = __shfl_sync(0xffffffffu, xq.x, g);
        float x1 = __shfl_sync(0xffffffffu, xq.y, g);
        float x2 = __shfl_sync(0xffffffffu, xq.z, g);
        float x3 = __shfl_sync(0xffffffffu, xq.w, g);
        const float* w0 = Ws + (g * 4) * C;
        a0 += x0 * w0[lane] + x1 * w0[C + lane] + x2 * w0[2 * C + lane] + x3 * w0[3 * C + lane];
        a1 += x0 * w0[cs] + x1 * w0[C + cs] + x2 * w0[2 * C + cs] + x3 * w0[3 * C + cs];
    }
    g_h2[(size_t)n * C + lane] = a0;
    if (has1) g_h2[(size_t)n * C + c1] = a1;
}

// ---------------------------------------------------------------------------
// Layer-2: warp-per-node gather (MLP-2) + self + bias + log_softmax -> out
// ---------------------------------------------------------------------------
__global__ __launch_bounds__(256) void k_agg2_gather(float* __restrict__ out,
                                                     const float* __restrict__ b2,
                                                     int N, int C) {
    int node = (blockIdx.x * blockDim.x + threadIdx.x) >> 5;
    int lane = threadIdx.x & 31;
    if (node >= N) return;
    int s = g_rs[node], e = s + g_cnt[node];
    float d = g_dinv[node];
    float dd = d * d;
    int c1 = lane + 32;
    bool has1 = c1 < C;
    const float* h0 = g_h2 + (size_t)node * C;
    float a0 = dd * h0[lane];
    float a1 = has1 ? dd * h0[c1] : 0.f;
    int t = s;
    for (; t + 2 <= e; t += 2) {
        uint2 p0 = g_epay[t], p1 = g_epay[t + 1];
        const float* hp0 = g_h2 + (size_t)p0.x * C;
        const float* hp1 = g_h2 + (size_t)p1.x * C;
        float n0 = __uint_as_float(p0.y), n1 = __uint_as_float(p1.y);
        a0 += n0 * hp0[lane] + n1 * hp1[lane];
        if (has1) a1 += n0 * hp0[c1] + n1 * hp1[c1];
    }
    for (; t < e; t++) {
        uint2 p = g_epay[t];
        float nr = __uint_as_float(p.y);
        const float* hp = g_h2 + (size_t)p.x * C;
        a0 += nr * hp[lane];
        if (has1) a1 += nr * hp[c1];
    }
    a0 += b2[lane];
    if (has1) a1 += b2[c1];
    const float NEG_INF = __int_as_float(0xff800000);
    float v1 = has1 ? a1 : NEG_INF;
    float m = fmaxf(a0, v1);
#pragma unroll
    for (int o = 16; o > 0; o >>= 1) m = fmaxf(m, __shfl_xor_sync(0xffffffffu, m, o));
    float sum = expf(a0 - m) + (has1 ? expf(a1 - m) : 0.f);
#pragma unroll
    for (int o = 16; o > 0; o >>= 1) sum += __shfl_xor_sync(0xffffffffu, sum, o);
    float l = logf(sum);
    float* z = out + (size_t)node * C;
    z[lane] = a0 - m - l;
    if (has1) z[c1] = a1 - m - l;
}

// ---------------------------------------------------------------------------
extern "C" void kernel_launch(void* const* d_in, const int* in_sizes, int n_in,
                              void* d_out, int out_size) {
    const float* feat = (const float*)d_in[0];
    const void*  ei   = d_in[1];
    const float* ew   = (const float*)d_in[2];
    const float* W1   = (const float*)d_in[3];
    const float* b1   = (const float*)d_in[4];
    const float* W2   = (const float*)d_in[5];
    const float* b2   = (const float*)d_in[6];
    float* out = (float*)d_out;

    int H   = in_sizes[4];
    int FIN = in_sizes[3] / H;
    int N   = in_sizes[0] / FIN;
    int C   = in_sizes[6];
    int E   = in_sizes[2];
    (void)n_in; (void)out_size;

    int nsb = (N + 1023) / 1024;
    int initb = ((N > FIN * 128 ? N : FIN * 128) + 255) / 256;
    int eb = (E + 255) / 256;
    long long MK4 = (long long)N * FIN / 4;
    long long convb = (MK4 + 255) / 256;
    long long grp = eb > (convb + 7) / 8 ? eb : (convb + 7) / 8;
    int dcgrid = (int)(grp * 9);

    cudaFuncSetAttribute(k_gemm1_mma, cudaFuncAttributeMaxDynamicSharedMemorySize, GSMEM);

    k_init_prep<<<initb, 256>>>((const unsigned int*)ei, (long long)2 * E, N, W1, FIN);
    k_deg_conv<<<dcgrid, 256>>>(ei, ew, E, feat, MK4, eb, convb);
    k_scan1<<<nsb, 1024>>>(N);
    k_gemm1_mma<<<(N + 127) / 128, 256, GSMEM>>>(N, FIN);
    k_scan2<<<nsb, 1024>>>(N);
    k_fill<<<(E + 255) / 256, 256>>>(ei, ew, E);

    k_agg1_gather<<<(N + 7) / 8, 256>>>(b1, N);
    k_gemm2<<<(N + 7) / 8, 256>>>(W2, N, C);
    k_agg2_gather<<<(N + 7) / 8, 256>>>(out, b2, N, C);
}